// round 13
// baseline (speedup 1.0000x reference)
#include <cuda_runtime.h>
#include <cuda_bf16.h>
#include <cstdint>
#include <math.h>

#define Nn 100000
#define Ee 1600000
#define Hh 128
#define Gg 512
#define TDd 256
#define NTILES 12500   // Ee / 128
#define EK_GRID 296

typedef unsigned long long ull;

// Scratch (device globals — no allocation allowed)
__device__ float g_agg[(size_t)Nn * Hh];
__device__ float g_h[(size_t)Nn * Hh];
__device__ float g_gamma[Gg * Hh];
__device__ float g_beta[Gg * Hh];

__device__ __forceinline__ float silu_f(float v) {
    return v * (1.0f / (1.0f + __expf(-v)));
}

// ---- packed f32x2 helpers --------------------------------------------------
__device__ __forceinline__ ull pack2(float x, float y) {
    ull r;
    asm("mov.b64 %0, {%1, %2};" : "=l"(r) : "f"(x), "f"(y));
    return r;
}
__device__ __forceinline__ void ffma2(ull& d, ull a, ull b) {
    asm("fma.rn.f32x2 %0, %1, %2, %0;" : "+l"(d) : "l"(a), "l"(b));
}
__device__ __forceinline__ float2 unpack2(ull v) {
    float2 r;
    asm("mov.b64 {%0, %1}, %2;" : "=f"(r.x), "=f"(r.y) : "l"(v));
    return r;
}

// ---- warp-level bf16 mma -----------------------------------------------------
__device__ __forceinline__ void mma_bf16(float* c, const uint32_t* a,
                                         uint32_t b0, uint32_t b1) {
    asm("mma.sync.aligned.m16n8k16.row.col.f32.bf16.bf16.f32 "
        "{%0,%1,%2,%3}, {%4,%5,%6,%7}, {%8,%9}, {%0,%1,%2,%3};"
        : "+f"(c[0]), "+f"(c[1]), "+f"(c[2]), "+f"(c[3])
        : "r"(a[0]), "r"(a[1]), "r"(a[2]), "r"(a[3]), "r"(b0), "r"(b1));
}

__device__ __forceinline__ void cvt8(const float* v, uint4* hi, uint4* lo) {
    uint32_t h[4], l[4];
#pragma unroll
    for (int i = 0; i < 4; ++i) {
        float a = v[2 * i], b = v[2 * i + 1];
        __nv_bfloat16 ha = __float2bfloat16(a), hb = __float2bfloat16(b);
        __nv_bfloat16 la = __float2bfloat16(a - __bfloat162float(ha));
        __nv_bfloat16 lb = __float2bfloat16(b - __bfloat162float(hb));
        h[i] = ((uint32_t)__bfloat16_as_ushort(hb) << 16) | (uint32_t)__bfloat16_as_ushort(ha);
        l[i] = ((uint32_t)__bfloat16_as_ushort(lb) << 16) | (uint32_t)__bfloat16_as_ushort(la);
    }
    *hi = make_uint4(h[0], h[1], h[2], h[3]);
    *lo = make_uint4(l[0], l[1], l[2], l[3]);
}

__device__ __forceinline__ void cvt2(float a, float b, uint32_t* hp, uint32_t* lp) {
    __nv_bfloat16 ha = __float2bfloat16(a), hb = __float2bfloat16(b);
    __nv_bfloat16 la = __float2bfloat16(a - __bfloat162float(ha));
    __nv_bfloat16 lb = __float2bfloat16(b - __bfloat162float(hb));
    *hp = ((uint32_t)__bfloat16_as_ushort(hb) << 16) | (uint32_t)__bfloat16_as_ushort(ha);
    *lp = ((uint32_t)__bfloat16_as_ushort(lb) << 16) | (uint32_t)__bfloat16_as_ushort(la);
}

// Stage a (col n, k-half ks) strip of B/W into FRAGMENT-ORDERED smem.
__device__ __forceinline__ void stage_bfrag(char* fh, char* fl, int n, int ks,
                                            const float* w) {
    uint4 h0, l0, h1, l1;
    cvt8(&w[0], &h0, &l0);
    cvt8(&w[8], &h1, &l1);
    const int nf = n >> 3, g = n & 7;
    uint32_t base = (uint32_t)(nf * 32 + g * 4) * 16 + (uint32_t)ks * 8;
    const uint32_t hw[4] = {h0.x, h0.y, h0.z, h0.w};
    const uint32_t hz[4] = {h1.x, h1.y, h1.z, h1.w};
    const uint32_t lw[4] = {l0.x, l0.y, l0.z, l0.w};
    const uint32_t lz[4] = {l1.x, l1.y, l1.z, l1.w};
#pragma unroll
    for (int t = 0; t < 4; ++t) {
        *(uint2*)(fh + base + t * 16) = make_uint2(hw[t], hz[t]);
        *(uint2*)(fl + base + t * 16) = make_uint2(lw[t], lz[t]);
    }
}

// ---------------------------------------------------------------------------
// 1) init: g_agg = x
// ---------------------------------------------------------------------------
__global__ void copy_kernel(const float* __restrict__ x) {
    size_t i = (size_t)blockIdx.x * blockDim.x + threadIdx.x;
    ((float4*)g_agg)[i] = ((const float4*)x)[i];
}

// ---------------------------------------------------------------------------
// 2) edge kernel v4: double-buffered pipeline, ONE sync per tile.
// ---------------------------------------------------------------------------
#define SBE   0
#define SSRC  512              // int[2][128] = 1024
#define SDST  1536             // int[2][128] = 1024
#define SFBH  2560             // 8192
#define SFBL  10752            // 8192
#define SAHI  18944            // [2] x 10240 = 20480
#define SALO  39424            // [2] x 10240 = 20480
#define EKSM  59904

__global__ __launch_bounds__(256, 2) void edge_kernel(
    const float* __restrict__ x, const int* __restrict__ ei,
    const float* __restrict__ ea, const float* __restrict__ We,
    const float* __restrict__ be) {
    extern __shared__ __align__(16) char smem[];
    const int tid = threadIdx.x;
    const int wid = tid >> 5;
    const int lane = tid & 31;

    float* be_s = (float*)(smem + SBE);
    int* src_s = (int*)(smem + SSRC);
    int* dst_s = (int*)(smem + SDST);

    if (tid < 128) be_s[tid] = be[tid];

    // stage B = We^T hi/lo in fragment order, once
    {
        int n = tid >> 1;
        int ks = tid & 1;
        float w[16];
#pragma unroll
        for (int j = 0; j < 16; ++j) w[j] = We[(size_t)(ks * 16 + j) * 128 + n];
        stage_bfrag(smem + SFBH, smem + SFBL, n, ks, w);
    }

    const int row = tid >> 1;
    const int ksh = tid & 1;

    // prologue: stage tile0 into buf 0
    {
        const int e0 = blockIdx.x * 128;
        const float* ap = ea + (size_t)(e0 + row) * 32 + ksh * 16;
        float v[16];
        *(float4*)&v[0]  = *(const float4*)(ap + 0);
        *(float4*)&v[4]  = *(const float4*)(ap + 4);
        *(float4*)&v[8]  = *(const float4*)(ap + 8);
        *(float4*)&v[12] = *(const float4*)(ap + 12);
        uint4 h0, l0, h1, l1;
        cvt8(&v[0], &h0, &l0);
        cvt8(&v[8], &h1, &l1);
        char* ah = smem + SAHI + row * 80 + ksh * 32;
        char* al = smem + SALO + row * 80 + ksh * 32;
        *(uint4*)ah = h0;  *(uint4*)(ah + 16) = h1;
        *(uint4*)al = l0;  *(uint4*)(al + 16) = l1;
        if (tid < 128) src_s[tid] = ei[e0 + tid];
        else           dst_s[tid - 128] = ei[Ee + e0 + (tid - 128)];
    }
    __syncthreads();

    const int g = lane >> 2;
    const int t = lane & 3;
    const int q = t >> 1;
    const int odd = t & 1;
    const int mb = wid * 16;

    int p = 0;
    for (int tile = blockIdx.x; tile < NTILES; tile += gridDim.x, p ^= 1) {
        const uint32_t Ao = (uint32_t)p * 10240;
        const int pb = p * 128;
        const int nb = (p ^ 1) * 128;

        // fragment loads from buf p
        uint32_t afh[2][4], afl[2][4];
        {
            const char* Ah = smem + SAHI + Ao + (mb + g) * 80 + t * 4;
            const char* Al = smem + SALO + Ao + (mb + g) * 80 + t * 4;
#pragma unroll
            for (int ks = 0; ks < 2; ++ks) {
                int o = ks * 32;
                afh[ks][0] = *(const uint32_t*)(Ah + o);
                afh[ks][1] = *(const uint32_t*)(Ah + o + 8 * 80);
                afh[ks][2] = *(const uint32_t*)(Ah + o + 16);
                afh[ks][3] = *(const uint32_t*)(Ah + o + 8 * 80 + 16);
                afl[ks][0] = *(const uint32_t*)(Al + o);
                afl[ks][1] = *(const uint32_t*)(Al + o + 8 * 80);
                afl[ks][2] = *(const uint32_t*)(Al + o + 16);
                afl[ks][3] = *(const uint32_t*)(Al + o + 8 * 80 + 16);
            }
        }

        float c[16][4];
#pragma unroll
        for (int nf = 0; nf < 16; ++nf) {
            c[nf][0] = 0.f; c[nf][1] = 0.f; c[nf][2] = 0.f; c[nf][3] = 0.f;
        }
#pragma unroll
        for (int nf = 0; nf < 16; ++nf) {
            uint4 BH = *(const uint4*)(smem + SFBH + (uint32_t)(nf * 32 + lane) * 16);
            uint4 BL = *(const uint4*)(smem + SFBL + (uint32_t)(nf * 32 + lane) * 16);
            mma_bf16(c[nf], afh[0], BH.x, BH.y);
            mma_bf16(c[nf], afh[1], BH.z, BH.w);
            mma_bf16(c[nf], afh[0], BL.x, BL.y);
            mma_bf16(c[nf], afh[1], BL.z, BL.w);
            mma_bf16(c[nf], afl[0], BH.x, BH.y);
            mma_bf16(c[nf], afl[1], BH.z, BH.w);
        }

        // issue next tile's global loads (latency overlapped with epilogue)
        const int ntile = tile + gridDim.x;
        const bool has_next = ntile < NTILES;
        float v[16];
        int sv = 0, dv = 0;
        if (has_next) {
            const int e0n = ntile * 128;
            const float* ap = ea + (size_t)(e0n + row) * 32 + ksh * 16;
            *(float4*)&v[0]  = *(const float4*)(ap + 0);
            *(float4*)&v[4]  = *(const float4*)(ap + 4);
            *(float4*)&v[8]  = *(const float4*)(ap + 8);
            *(float4*)&v[12] = *(const float4*)(ap + 12);
            if (tid < 128) sv = ei[e0n + tid];
            else           dv = ei[Ee + e0n + (tid - 128)];
        }

        // epilogue: gather x[src] + relu + red into g_agg (buf p src/dst)
#pragma unroll
        for (int rs = 0; rs < 2; ++rs) {
            const int el = mb + g + rs * 8;
            const int s = src_s[pb + el];
            const int d = dst_s[pb + el];
            const float* xb = x + (size_t)s * 128;
            float* ob = g_agg + (size_t)d * 128;
#pragma unroll
            for (int pp = 0; pp < 8; ++pp) {
                const int nfe = 2 * pp, nfo = 2 * pp + 1;
                float2 me, mo;
                me.x = c[nfe][rs * 2]; me.y = c[nfe][rs * 2 + 1];
                mo.x = c[nfo][rs * 2]; mo.y = c[nfo][rs * 2 + 1];
                ull send = odd ? pack2(me.x, me.y) : pack2(mo.x, mo.y);
                ull recv = __shfl_xor_sync(0xFFFFFFFFu, send, 1);
                float2 rv = unpack2(recv);
                const int nf = odd ? nfo : nfe;
                float2 lo2 = odd ? rv : me;
                float2 hi2 = odd ? mo : rv;
                const int col = nf * 8 + q * 4;
                float4 xv = *(const float4*)(xb + col);
                float4 bv = *(const float4*)&be_s[col];
                float r0 = fmaxf(xv.x + lo2.x + bv.x, 0.f);
                float r1 = fmaxf(xv.y + lo2.y + bv.y, 0.f);
                float r2 = fmaxf(xv.z + hi2.x + bv.z, 0.f);
                float r3 = fmaxf(xv.w + hi2.y + bv.w, 0.f);
                asm volatile("red.global.add.v4.f32 [%0], {%1,%2,%3,%4};"
                             :: "l"(ob + col), "f"(r0), "f"(r1), "f"(r2), "f"(r3)
                             : "memory");
            }
        }

        // store staged next tile into buf 1-p
        if (has_next) {
            uint4 h0, l0, h1, l1;
            cvt8(&v[0], &h0, &l0);
            cvt8(&v[8], &h1, &l1);
            const uint32_t An = (uint32_t)(p ^ 1) * 10240;
            char* ah = smem + SAHI + An + row * 80 + ksh * 32;
            char* al = smem + SALO + An + row * 80 + ksh * 32;
            *(uint4*)ah = h0;  *(uint4*)(ah + 16) = h1;
            *(uint4*)al = l0;  *(uint4*)(al + 16) = l1;
            if (tid < 128) src_s[nb + tid] = sv;
            else           dst_s[nb + (tid - 128)] = dv;
        }
        __syncthreads();
    }
}

// ---------------------------------------------------------------------------
// 3) fused node MLP (R8 proven: smem-staged A, frag-ordered W)
// ---------------------------------------------------------------------------
#define MP 272
#define MS_AHI 0
#define MS_ALO 34816
#define MS_WFH 69632
#define MS_WFL 77824
#define MS_B1  86016
#define MS_B2  86528
#define MLP_SMEM 87040

extern "C" __global__ __launch_bounds__(256) void mlp_kernel(
    const float* __restrict__ W1, const float* __restrict__ b1,
    const float* __restrict__ W2, const float* __restrict__ b2) {
    extern __shared__ __align__(16) char msm[];
    const int tid = threadIdx.x;
    const int wid = tid >> 5;
    const int lane = tid & 31;
    const int g = lane >> 2;
    const int t = lane & 3;
    const int q = t >> 1;
    const int odd = t & 1;
    const int mb = wid * 16;
    const int r0 = blockIdx.x * 128;

    float* b1s = (float*)(msm + MS_B1);
    float* b2s = (float*)(msm + MS_B2);
    if (tid < 128) b1s[tid] = b1[tid];
    else           b2s[tid - 128] = b2[tid - 128];

    {
        int row = tid >> 1;
        int half = tid & 1;
        int node = r0 + row;
        const float* ap = g_agg + (size_t)node * 128 + half * 64;
#pragma unroll
        for (int gi = 0; gi < 4; ++gi) {
            float v[16];
            if (node < Nn) {
                *(float4*)&v[0]  = *(const float4*)(ap + gi * 16 + 0);
                *(float4*)&v[4]  = *(const float4*)(ap + gi * 16 + 4);
                *(float4*)&v[8]  = *(const float4*)(ap + gi * 16 + 8);
                *(float4*)&v[12] = *(const float4*)(ap + gi * 16 + 12);
            } else {
#pragma unroll
                for (int j = 0; j < 16; ++j) v[j] = 0.f;
            }
            uint4 h0, l0, h1, l1;
            cvt8(&v[0], &h0, &l0);
            cvt8(&v[8], &h1, &l1);
            uint32_t off = (uint32_t)row * MP + (uint32_t)(half * 64 + gi * 16) * 2;
            *(uint4*)(msm + MS_AHI + off)      = h0;
            *(uint4*)(msm + MS_AHI + off + 16) = h1;
            *(uint4*)(msm + MS_ALO + off)      = l0;
            *(uint4*)(msm + MS_ALO + off + 16) = l1;
        }
    }
    __syncthreads();

    float c[16][4];
#pragma unroll
    for (int nf = 0; nf < 16; ++nf) {
        c[nf][0] = 0.f; c[nf][1] = 0.f; c[nf][2] = 0.f; c[nf][3] = 0.f;
    }

    for (int lyr = 0; lyr < 2; ++lyr) {
        const float* W = (lyr == 0) ? W1 : W2;

        for (int kc = 0; kc < 128; kc += 32) {
            {
                int n = tid >> 1;
                int ks = tid & 1;
                float w[16];
#pragma unroll
                for (int j = 0; j < 16; ++j)
                    w[j] = W[(size_t)(kc + ks * 16 + j) * 128 + n];
                stage_bfrag(msm + MS_WFH, msm + MS_WFL, n, ks, w);
            }
            __syncthreads();

            uint32_t afh[2][4], afl[2][4];
            {
                const char* Ah = msm + MS_AHI + (mb + g) * MP + kc * 2 + t * 4;
                const char* Al = msm + MS_ALO + (mb + g) * MP + kc * 2 + t * 4;
#pragma unroll
                for (int ks = 0; ks < 2; ++ks) {
                    int o = ks * 32;
                    afh[ks][0] = *(const uint32_t*)(Ah + o);
                    afh[ks][1] = *(const uint32_t*)(Ah + o + 8 * MP);
                    afh[ks][2] = *(const uint32_t*)(Ah + o + 16);
                    afh[ks][3] = *(const uint32_t*)(Ah + o + 8 * MP + 16);
                    afl[ks][0] = *(const uint32_t*)(Al + o);
                    afl[ks][1] = *(const uint32_t*)(Al + o + 8 * MP);
                    afl[ks][2] = *(const uint32_t*)(Al + o + 16);
                    afl[ks][3] = *(const uint32_t*)(Al + o + 8 * MP + 16);
                }
            }

#pragma unroll
            for (int nf = 0; nf < 16; ++nf) {
                uint4 BH = *(const uint4*)(msm + MS_WFH + (uint32_t)(nf * 32 + lane) * 16);
                uint4 BL = *(const uint4*)(msm + MS_WFL + (uint32_t)(nf * 32 + lane) * 16);
                mma_bf16(c[nf], afh[0], BH.x, BH.y);
                mma_bf16(c[nf], afh[1], BH.z, BH.w);
                mma_bf16(c[nf], afh[0], BL.x, BL.y);
                mma_bf16(c[nf], afh[1], BL.z, BL.w);
                mma_bf16(c[nf], afl[0], BH.x, BH.y);
                mma_bf16(c[nf], afl[1], BH.z, BH.w);
            }
            __syncthreads();
        }

        if (lyr == 0) {
#pragma unroll
            for (int nf = 0; nf < 16; ++nf) {
#pragma unroll
                for (int rs = 0; rs < 2; ++rs) {
                    int row = mb + g + rs * 8;
                    int col = nf * 8 + 2 * t;
                    float m0 = silu_f(c[nf][rs * 2] + b1s[col]);
                    float m1 = silu_f(c[nf][rs * 2 + 1] + b1s[col + 1]);
                    uint32_t hp, lp;
                    cvt2(m0, m1, &hp, &lp);
                    uint32_t off = (uint32_t)row * MP + (uint32_t)col * 2;
                    *(uint32_t*)(msm + MS_AHI + off) = hp;
                    *(uint32_t*)(msm + MS_ALO + off) = lp;
                    c[nf][rs * 2] = 0.f;
                    c[nf][rs * 2 + 1] = 0.f;
                }
            }
            __syncthreads();
        }
    }

#pragma unroll
    for (int rs = 0; rs < 2; ++rs) {
        const int node = r0 + mb + g + rs * 8;
        float* ob = g_h + (size_t)node * 128;
#pragma unroll
        for (int p = 0; p < 8; ++p) {
            const int nfe = 2 * p, nfo = 2 * p + 1;
            float2 me, mo;
            me.x = c[nfe][rs * 2]; me.y = c[nfe][rs * 2 + 1];
            mo.x = c[nfo][rs * 2]; mo.y = c[nfo][rs * 2 + 1];
            ull send = odd ? pack2(me.x, me.y) : pack2(mo.x, mo.y);
            ull recv = __shfl_xor_sync(0xFFFFFFFFu, send, 1);
            float2 rv = unpack2(recv);
            const int nf = odd ? nfo : nfe;
            float2 lo2 = odd ? rv : me;
            float2 hi2 = odd ? mo : rv;
            const int col = nf * 8 + q * 4;
            if (node < Nn) {
                float4 o;
                o.x = lo2.x + b2s[col + 0];
                o.y = lo2.y + b2s[col + 1];
                o.z = hi2.x + b2s[col + 2];
                o.w = hi2.y + b2s[col + 3];
                *(float4*)(ob + col) = o;
            }
        }
    }
}

// ---------------------------------------------------------------------------
// 4) FiLM params: 2 graphs per block (proven config)
// ---------------------------------------------------------------------------
__global__ __launch_bounds__(256) void film_kernel(
    const float* __restrict__ te,
    const float* __restrict__ Wg, const float* __restrict__ bg,
    const float* __restrict__ Wb, const float* __restrict__ bb) {
    __shared__ float tes[256][2];
    const int tid = threadIdx.x;
    const int g0 = blockIdx.x * 2;

    if (tid < 128) {
        int g = tid >> 6, c4 = (tid & 63) * 4;
        float4 v = *(const float4*)&te[(size_t)(g0 + g) * 256 + c4];
        tes[c4 + 0][g] = v.x;
        tes[c4 + 1][g] = v.y;
        tes[c4 + 2][g] = v.z;
        tes[c4 + 3][g] = v.w;
    }
    __syncthreads();

    const int f = tid & 127;
    const int half = tid >> 7;
    const float* W = half ? Wb : Wg;

    ull acc0 = 0ULL, acc1 = 0ULL;
#pragma unroll 8
    for (int k = 0; k < 256; k += 2) {
        float w0 = W[(size_t)k * 128 + f];
        float w1 = W[(size_t)(k + 1) * 128 + f];
        ull t0 = *reinterpret_cast<const ull*>(&tes[k][0]);
        ull t1 = *reinterpret_cast<const ull*>(&tes[k + 1][0]);
        ffma2(acc0, pack2(w0, w0), t0);
        ffma2(acc1, pack2(w1, w1), t1);
    }
    float2 p0 = unpack2(acc0), p1 = unpack2(acc1);
    float add = half ? bb[f] : (bg[f] + 1.0f);
    float* dst = half ? g_beta : g_gamma;
    dst[(g0 + 0) * 128 + f] = p0.x + p1.x + add;
    dst[(g0 + 1) * 128 + f] = p0.y + p1.y + add;
}

// ---------------------------------------------------------------------------
// 5) fused GraphNorm stats + FiLM apply + silu + residual (block per graph)
// ---------------------------------------------------------------------------
__global__ __launch_bounds__(128) void normfinal_kernel(
    const float* __restrict__ x, const int* __restrict__ batch,
    const float* __restrict__ ms,
    const float* __restrict__ gnw, const float* __restrict__ gnb,
    float* __restrict__ out) {
    __shared__ int bounds[2];
    const int g = blockIdx.x;
    if (threadIdx.x < 2) {
        int target = g + threadIdx.x;
        int lo = 0, hi = Nn;
        while (lo < hi) {
            int mid = (lo + hi) >> 1;
            if (batch[mid] < target) lo = mid + 1; else hi = mid;
        }
        bounds[threadIdx.x] = lo;
    }
    __syncthreads();
    const int s = bounds[0], e = bounds[1];
    const int f = threadIdx.x;

    // pass 1: per-feature sum / sumsq over this graph's rows
    float sum0 = 0.f, sq0 = 0.f, sum1 = 0.f, sq1 = 0.f;
    float sum2 = 0.f, sq2 = 0.f, sum3 = 0.f, sq3 = 0.f;
    int n = s;
    for (; n + 3 < e; n += 4) {
        float v0 = g_h[(size_t)n * 128 + f];
        float v1 = g_h[(size_t)(n + 1) * 128 + f];
        float v2 = g_h[(size_t)(n + 2) * 128 + f];
        float v3 = g_h[(size_t)(n + 3) * 128 + f];
        sum0 += v0; sq0 += v0 * v0;
        sum1 += v1; sq1 += v1 * v1;
        sum2 += v2; sq2 += v2 * v2;
        sum3 += v3; sq3 += v3 * v3;
    }
    for (; n < e; ++n) {
        float v0 = g_h[(size_t)n * 128 + f];
        sum0 += v0; sq0 += v0 * v0;
    }
    float sum = (sum0 + sum1) + (sum2 + sum3);
    float sq = (sq0 + sq1) + (sq2 + sq3);

    float ccount = fmaxf((float)(e - s), 1.f);
    float mean = sum / ccount;
    float m2 = sq / ccount;
    float msf = ms[f];
    float var = m2 - (2.f * msf - msf * msf) * mean * mean;
    var = fmaxf(var, 0.f);
    float msub = mean * msf;
    float rstd = rsqrtf(var + 1e-5f);

    float gm = g_gamma[g * 128 + f];
    float bt = g_beta[g * 128 + f];
    float w = gnw[f];
    float b = gnb[f];
    // fold constants: out = x + silu( (gm*w*rstd)*h + (gm*(b - w*msub*rstd) + bt) )
    float kA = gm * w * rstd;
    float kB = gm * (b - w * msub * rstd) + bt;

    // pass 2 (L2-hot): normalize + film + silu + residual
    for (n = s; n < e; ++n) {
        float h = g_h[(size_t)n * 128 + f];
        float xv = x[(size_t)n * 128 + f];
        float v = kA * h + kB;
        out[(size_t)n * 128 + f] = xv + silu_f(v);
    }
}

// ---------------------------------------------------------------------------
extern "C" void kernel_launch(void* const* d_in, const int* in_sizes, int n_in,
                              void* d_out, int out_size) {
    const float* x   = (const float*)d_in[0];
    const int*   ei  = (const int*)d_in[1];
    const float* ea  = (const float*)d_in[2];
    const int*   bat = (const int*)d_in[3];
    const float* te  = (const float*)d_in[4];
    const float* We  = (const float*)d_in[5];
    const float* be  = (const float*)d_in[6];
    const float* W1  = (const float*)d_in[7];
    const float* b1  = (const float*)d_in[8];
    const float* W2  = (const float*)d_in[9];
    const float* b2  = (const float*)d_in[10];
    const float* gnw = (const float*)d_in[11];
    const float* gnb = (const float*)d_in[12];
    const float* gms = (const float*)d_in[13];
    const float* Wg  = (const float*)d_in[14];
    const float* bg  = (const float*)d_in[15];
    const float* Wb  = (const float*)d_in[16];
    const float* bb  = (const float*)d_in[17];
    float* out = (float*)d_out;

    cudaFuncSetAttribute((const void*)edge_kernel,
                         cudaFuncAttributeMaxDynamicSharedMemorySize, EKSM);
    cudaFuncSetAttribute((const void*)mlp_kernel,
                         cudaFuncAttributeMaxDynamicSharedMemorySize, MLP_SMEM);

    copy_kernel<<<12500, 256>>>(x);
    edge_kernel<<<EK_GRID, 256, EKSM>>>(x, ei, ea, We, be);
    mlp_kernel<<<(Nn + 127) / 128, 256, MLP_SMEM>>>(W1, b1, W2, b2);
    film_kernel<<<Gg / 2, 256>>>(te, Wg, bg, Wb, bb);
    normfinal_kernel<<<Gg, 128>>>(x, bat, gms, gnw, gnb, out);
}

// round 14
// speedup vs baseline: 1.0184x; 1.0184x over previous
#include <cuda_runtime.h>
#include <cuda_bf16.h>
#include <cstdint>
#include <math.h>

#define Nn 100000
#define Ee 1600000
#define Hh 128
#define Gg 512
#define TDd 256
#define NTILES 12500   // Ee / 128
#define EK_GRID 296

typedef unsigned long long ull;

// Scratch (device globals — no allocation allowed)
__device__ float g_agg[(size_t)Nn * Hh];
__device__ float g_h[(size_t)Nn * Hh];
__device__ float g_gamma[Gg * Hh];
__device__ float g_beta[Gg * Hh];

__device__ __forceinline__ float silu_f(float v) {
    return v * (1.0f / (1.0f + __expf(-v)));
}

// ---- packed f32x2 helpers --------------------------------------------------
__device__ __forceinline__ ull pack2(float x, float y) {
    ull r;
    asm("mov.b64 %0, {%1, %2};" : "=l"(r) : "f"(x), "f"(y));
    return r;
}
__device__ __forceinline__ void ffma2(ull& d, ull a, ull b) {
    asm("fma.rn.f32x2 %0, %1, %2, %0;" : "+l"(d) : "l"(a), "l"(b));
}
__device__ __forceinline__ float2 unpack2(ull v) {
    float2 r;
    asm("mov.b64 {%0, %1}, %2;" : "=f"(r.x), "=f"(r.y) : "l"(v));
    return r;
}

// ---- warp-level bf16 mma -----------------------------------------------------
__device__ __forceinline__ void mma_bf16(float* c, const uint32_t* a,
                                         uint32_t b0, uint32_t b1) {
    asm("mma.sync.aligned.m16n8k16.row.col.f32.bf16.bf16.f32 "
        "{%0,%1,%2,%3}, {%4,%5,%6,%7}, {%8,%9}, {%0,%1,%2,%3};"
        : "+f"(c[0]), "+f"(c[1]), "+f"(c[2]), "+f"(c[3])
        : "r"(a[0]), "r"(a[1]), "r"(a[2]), "r"(a[3]), "r"(b0), "r"(b1));
}

__device__ __forceinline__ void cvt8(const float* v, uint4* hi, uint4* lo) {
    uint32_t h[4], l[4];
#pragma unroll
    for (int i = 0; i < 4; ++i) {
        float a = v[2 * i], b = v[2 * i + 1];
        __nv_bfloat16 ha = __float2bfloat16(a), hb = __float2bfloat16(b);
        __nv_bfloat16 la = __float2bfloat16(a - __bfloat162float(ha));
        __nv_bfloat16 lb = __float2bfloat16(b - __bfloat162float(hb));
        h[i] = ((uint32_t)__bfloat16_as_ushort(hb) << 16) | (uint32_t)__bfloat16_as_ushort(ha);
        l[i] = ((uint32_t)__bfloat16_as_ushort(lb) << 16) | (uint32_t)__bfloat16_as_ushort(la);
    }
    *hi = make_uint4(h[0], h[1], h[2], h[3]);
    *lo = make_uint4(l[0], l[1], l[2], l[3]);
}

__device__ __forceinline__ void cvt2(float a, float b, uint32_t* hp, uint32_t* lp) {
    __nv_bfloat16 ha = __float2bfloat16(a), hb = __float2bfloat16(b);
    __nv_bfloat16 la = __float2bfloat16(a - __bfloat162float(ha));
    __nv_bfloat16 lb = __float2bfloat16(b - __bfloat162float(hb));
    *hp = ((uint32_t)__bfloat16_as_ushort(hb) << 16) | (uint32_t)__bfloat16_as_ushort(ha);
    *lp = ((uint32_t)__bfloat16_as_ushort(lb) << 16) | (uint32_t)__bfloat16_as_ushort(la);
}

// Stage a (col n, k-half ks) strip of B/W into FRAGMENT-ORDERED smem.
__device__ __forceinline__ void stage_bfrag(char* fh, char* fl, int n, int ks,
                                            const float* w) {
    uint4 h0, l0, h1, l1;
    cvt8(&w[0], &h0, &l0);
    cvt8(&w[8], &h1, &l1);
    const int nf = n >> 3, g = n & 7;
    uint32_t base = (uint32_t)(nf * 32 + g * 4) * 16 + (uint32_t)ks * 8;
    const uint32_t hw[4] = {h0.x, h0.y, h0.z, h0.w};
    const uint32_t hz[4] = {h1.x, h1.y, h1.z, h1.w};
    const uint32_t lw[4] = {l0.x, l0.y, l0.z, l0.w};
    const uint32_t lz[4] = {l1.x, l1.y, l1.z, l1.w};
#pragma unroll
    for (int t = 0; t < 4; ++t) {
        *(uint2*)(fh + base + t * 16) = make_uint2(hw[t], hz[t]);
        *(uint2*)(fl + base + t * 16) = make_uint2(lw[t], lz[t]);
    }
}

// edge kernel smem layout (bytes) — R8 proven
#define SBE   0
#define SSRC  512
#define SDST  1024
#define SAHI  1536
#define SALO  (SAHI + 10240)
#define SFBH  (SALO + 10240)
#define SFBL  (SFBH + 8192)
#define EKSM  (SFBL + 8192)

// ---------------------------------------------------------------------------
// 1) init: g_agg = x
// ---------------------------------------------------------------------------
__global__ void copy_kernel(const float* __restrict__ x) {
    size_t i = (size_t)blockIdx.x * blockDim.x + threadIdx.x;
    ((float4*)g_agg)[i] = ((const float4*)x)[i];
}

// ---------------------------------------------------------------------------
// 2) edge kernel (R8 proven): persistent split-bf16 mma GEMM + gather/relu/red
// ---------------------------------------------------------------------------
__global__ __launch_bounds__(256, 2) void edge_kernel(
    const float* __restrict__ x, const int* __restrict__ ei,
    const float* __restrict__ ea, const float* __restrict__ We,
    const float* __restrict__ be) {
    __shared__ __align__(16) char smem[EKSM];
    const int tid = threadIdx.x;
    const int wid = tid >> 5;
    const int lane = tid & 31;

    float* be_s = (float*)(smem + SBE);
    int* src_s = (int*)(smem + SSRC);
    int* dst_s = (int*)(smem + SDST);

    if (tid < 128) be_s[tid] = be[tid];

    {
        int n = tid >> 1;
        int ks = tid & 1;
        float w[16];
#pragma unroll
        for (int j = 0; j < 16; ++j) w[j] = We[(size_t)(ks * 16 + j) * 128 + n];
        stage_bfrag(smem + SFBH, smem + SFBL, n, ks, w);
    }
    __syncthreads();

    const int g = lane >> 2;
    const int t = lane & 3;
    const int q = t >> 1;
    const int odd = t & 1;
    const int mb = wid * 16;

    for (int tile = blockIdx.x; tile < NTILES; tile += gridDim.x) {
        const int e0 = tile * 128;

        if (tid < 128) src_s[tid] = ei[e0 + tid];
        else           dst_s[tid - 128] = ei[Ee + e0 + (tid - 128)];

        {
            int row = tid >> 1;
            int ks = tid & 1;
            const float* ap = ea + (size_t)(e0 + row) * 32 + ks * 16;
            float v[16];
            *(float4*)&v[0]  = *(const float4*)(ap + 0);
            *(float4*)&v[4]  = *(const float4*)(ap + 4);
            *(float4*)&v[8]  = *(const float4*)(ap + 8);
            *(float4*)&v[12] = *(const float4*)(ap + 12);
            uint4 h0, l0, h1, l1;
            cvt8(&v[0], &h0, &l0);
            cvt8(&v[8], &h1, &l1);
            char* ah = smem + SAHI + row * 80 + ks * 32;
            char* al = smem + SALO + row * 80 + ks * 32;
            *(uint4*)ah = h0;  *(uint4*)(ah + 16) = h1;
            *(uint4*)al = l0;  *(uint4*)(al + 16) = l1;
        }
        __syncthreads();

        uint32_t afh[2][4], afl[2][4];
        {
            const char* Ah = smem + SAHI + (mb + g) * 80 + t * 4;
            const char* Al = smem + SALO + (mb + g) * 80 + t * 4;
#pragma unroll
            for (int ks = 0; ks < 2; ++ks) {
                int o = ks * 32;
                afh[ks][0] = *(const uint32_t*)(Ah + o);
                afh[ks][1] = *(const uint32_t*)(Ah + o + 8 * 80);
                afh[ks][2] = *(const uint32_t*)(Ah + o + 16);
                afh[ks][3] = *(const uint32_t*)(Ah + o + 8 * 80 + 16);
                afl[ks][0] = *(const uint32_t*)(Al + o);
                afl[ks][1] = *(const uint32_t*)(Al + o + 8 * 80);
                afl[ks][2] = *(const uint32_t*)(Al + o + 16);
                afl[ks][3] = *(const uint32_t*)(Al + o + 8 * 80 + 16);
            }
        }

        float c[16][4];
#pragma unroll
        for (int nf = 0; nf < 16; ++nf) {
            c[nf][0] = 0.f; c[nf][1] = 0.f; c[nf][2] = 0.f; c[nf][3] = 0.f;
        }

#pragma unroll
        for (int nf = 0; nf < 16; ++nf) {
            uint4 BH = *(const uint4*)(smem + SFBH + (uint32_t)(nf * 32 + lane) * 16);
            uint4 BL = *(const uint4*)(smem + SFBL + (uint32_t)(nf * 32 + lane) * 16);
            mma_bf16(c[nf], afh[0], BH.x, BH.y);
            mma_bf16(c[nf], afh[1], BH.z, BH.w);
            mma_bf16(c[nf], afh[0], BL.x, BL.y);
            mma_bf16(c[nf], afh[1], BL.z, BL.w);
            mma_bf16(c[nf], afl[0], BH.x, BH.y);
            mma_bf16(c[nf], afl[1], BH.z, BH.w);
        }

#pragma unroll
        for (int rs = 0; rs < 2; ++rs) {
            const int el = mb + g + rs * 8;
            const int s = src_s[el];
            const int d = dst_s[el];
            const float* xb = x + (size_t)s * 128;
            float* ob = g_agg + (size_t)d * 128;
#pragma unroll
            for (int p = 0; p < 8; ++p) {
                const int nfe = 2 * p, nfo = 2 * p + 1;
                float2 me, mo;
                me.x = c[nfe][rs * 2]; me.y = c[nfe][rs * 2 + 1];
                mo.x = c[nfo][rs * 2]; mo.y = c[nfo][rs * 2 + 1];
                ull send = odd ? pack2(me.x, me.y) : pack2(mo.x, mo.y);
                ull recv = __shfl_xor_sync(0xFFFFFFFFu, send, 1);
                float2 rv = unpack2(recv);
                const int nf = odd ? nfo : nfe;
                float2 lo2 = odd ? rv : me;
                float2 hi2 = odd ? mo : rv;
                const int col = nf * 8 + q * 4;
                float4 xv = *(const float4*)(xb + col);
                float4 bv = *(const float4*)&be_s[col];
                float r0 = fmaxf(xv.x + lo2.x + bv.x, 0.f);
                float r1 = fmaxf(xv.y + lo2.y + bv.y, 0.f);
                float r2 = fmaxf(xv.z + hi2.x + bv.z, 0.f);
                float r3 = fmaxf(xv.w + hi2.y + bv.w, 0.f);
                asm volatile("red.global.add.v4.f32 [%0], {%1,%2,%3,%4};"
                             :: "l"(ob + col), "f"(r0), "f"(r1), "f"(r2), "f"(r3)
                             : "memory");
            }
        }
        __syncthreads();
    }
}

// ---------------------------------------------------------------------------
// 3) fused node MLP (R8 proven: smem-staged A, frag-ordered W)
// ---------------------------------------------------------------------------
#define MP 272
#define MS_AHI 0
#define MS_ALO 34816
#define MS_WFH 69632
#define MS_WFL 77824
#define MS_B1  86016
#define MS_B2  86528
#define MLP_SMEM 87040

extern "C" __global__ __launch_bounds__(256) void mlp_kernel(
    const float* __restrict__ W1, const float* __restrict__ b1,
    const float* __restrict__ W2, const float* __restrict__ b2) {
    extern __shared__ __align__(16) char msm[];
    const int tid = threadIdx.x;
    const int wid = tid >> 5;
    const int lane = tid & 31;
    const int g = lane >> 2;
    const int t = lane & 3;
    const int q = t >> 1;
    const int odd = t & 1;
    const int mb = wid * 16;
    const int r0 = blockIdx.x * 128;

    float* b1s = (float*)(msm + MS_B1);
    float* b2s = (float*)(msm + MS_B2);
    if (tid < 128) b1s[tid] = b1[tid];
    else           b2s[tid - 128] = b2[tid - 128];

    {
        int row = tid >> 1;
        int half = tid & 1;
        int node = r0 + row;
        const float* ap = g_agg + (size_t)node * 128 + half * 64;
#pragma unroll
        for (int gi = 0; gi < 4; ++gi) {
            float v[16];
            if (node < Nn) {
                *(float4*)&v[0]  = *(const float4*)(ap + gi * 16 + 0);
                *(float4*)&v[4]  = *(const float4*)(ap + gi * 16 + 4);
                *(float4*)&v[8]  = *(const float4*)(ap + gi * 16 + 8);
                *(float4*)&v[12] = *(const float4*)(ap + gi * 16 + 12);
            } else {
#pragma unroll
                for (int j = 0; j < 16; ++j) v[j] = 0.f;
            }
            uint4 h0, l0, h1, l1;
            cvt8(&v[0], &h0, &l0);
            cvt8(&v[8], &h1, &l1);
            uint32_t off = (uint32_t)row * MP + (uint32_t)(half * 64 + gi * 16) * 2;
            *(uint4*)(msm + MS_AHI + off)      = h0;
            *(uint4*)(msm + MS_AHI + off + 16) = h1;
            *(uint4*)(msm + MS_ALO + off)      = l0;
            *(uint4*)(msm + MS_ALO + off + 16) = l1;
        }
    }
    __syncthreads();

    float c[16][4];
#pragma unroll
    for (int nf = 0; nf < 16; ++nf) {
        c[nf][0] = 0.f; c[nf][1] = 0.f; c[nf][2] = 0.f; c[nf][3] = 0.f;
    }

    for (int lyr = 0; lyr < 2; ++lyr) {
        const float* W = (lyr == 0) ? W1 : W2;

        for (int kc = 0; kc < 128; kc += 32) {
            {
                int n = tid >> 1;
                int ks = tid & 1;
                float w[16];
#pragma unroll
                for (int j = 0; j < 16; ++j)
                    w[j] = W[(size_t)(kc + ks * 16 + j) * 128 + n];
                stage_bfrag(msm + MS_WFH, msm + MS_WFL, n, ks, w);
            }
            __syncthreads();

            uint32_t afh[2][4], afl[2][4];
            {
                const char* Ah = msm + MS_AHI + (mb + g) * MP + kc * 2 + t * 4;
                const char* Al = msm + MS_ALO + (mb + g) * MP + kc * 2 + t * 4;
#pragma unroll
                for (int ks = 0; ks < 2; ++ks) {
                    int o = ks * 32;
                    afh[ks][0] = *(const uint32_t*)(Ah + o);
                    afh[ks][1] = *(const uint32_t*)(Ah + o + 8 * MP);
                    afh[ks][2] = *(const uint32_t*)(Ah + o + 16);
                    afh[ks][3] = *(const uint32_t*)(Ah + o + 8 * MP + 16);
                    afl[ks][0] = *(const uint32_t*)(Al + o);
                    afl[ks][1] = *(const uint32_t*)(Al + o + 8 * MP);
                    afl[ks][2] = *(const uint32_t*)(Al + o + 16);
                    afl[ks][3] = *(const uint32_t*)(Al + o + 8 * MP + 16);
                }
            }

#pragma unroll
            for (int nf = 0; nf < 16; ++nf) {
                uint4 BH = *(const uint4*)(msm + MS_WFH + (uint32_t)(nf * 32 + lane) * 16);
                uint4 BL = *(const uint4*)(msm + MS_WFL + (uint32_t)(nf * 32 + lane) * 16);
                mma_bf16(c[nf], afh[0], BH.x, BH.y);
                mma_bf16(c[nf], afh[1], BH.z, BH.w);
                mma_bf16(c[nf], afh[0], BL.x, BL.y);
                mma_bf16(c[nf], afh[1], BL.z, BL.w);
                mma_bf16(c[nf], afl[0], BH.x, BH.y);
                mma_bf16(c[nf], afl[1], BH.z, BH.w);
            }
            __syncthreads();
        }

        if (lyr == 0) {
#pragma unroll
            for (int nf = 0; nf < 16; ++nf) {
#pragma unroll
                for (int rs = 0; rs < 2; ++rs) {
                    int row = mb + g + rs * 8;
                    int col = nf * 8 + 2 * t;
                    float m0 = silu_f(c[nf][rs * 2] + b1s[col]);
                    float m1 = silu_f(c[nf][rs * 2 + 1] + b1s[col + 1]);
                    uint32_t hp, lp;
                    cvt2(m0, m1, &hp, &lp);
                    uint32_t off = (uint32_t)row * MP + (uint32_t)col * 2;
                    *(uint32_t*)(msm + MS_AHI + off) = hp;
                    *(uint32_t*)(msm + MS_ALO + off) = lp;
                    c[nf][rs * 2] = 0.f;
                    c[nf][rs * 2 + 1] = 0.f;
                }
            }
            __syncthreads();
        }
    }

#pragma unroll
    for (int rs = 0; rs < 2; ++rs) {
        const int node = r0 + mb + g + rs * 8;
        float* ob = g_h + (size_t)node * 128;
#pragma unroll
        for (int p = 0; p < 8; ++p) {
            const int nfe = 2 * p, nfo = 2 * p + 1;
            float2 me, mo;
            me.x = c[nfe][rs * 2]; me.y = c[nfe][rs * 2 + 1];
            mo.x = c[nfo][rs * 2]; mo.y = c[nfo][rs * 2 + 1];
            ull send = odd ? pack2(me.x, me.y) : pack2(mo.x, mo.y);
            ull recv = __shfl_xor_sync(0xFFFFFFFFu, send, 1);
            float2 rv = unpack2(recv);
            const int nf = odd ? nfo : nfe;
            float2 lo2 = odd ? rv : me;
            float2 hi2 = odd ? mo : rv;
            const int col = nf * 8 + q * 4;
            if (node < Nn) {
                float4 o;
                o.x = lo2.x + b2s[col + 0];
                o.y = lo2.y + b2s[col + 1];
                o.z = hi2.x + b2s[col + 2];
                o.w = hi2.y + b2s[col + 3];
                *(float4*)(ob + col) = o;
            }
        }
    }
}

// ---------------------------------------------------------------------------
// 4) FiLM params: 2 graphs per block (proven config)
// ---------------------------------------------------------------------------
__global__ __launch_bounds__(256) void film_kernel(
    const float* __restrict__ te,
    const float* __restrict__ Wg, const float* __restrict__ bg,
    const float* __restrict__ Wb, const float* __restrict__ bb) {
    __shared__ float tes[256][2];
    const int tid = threadIdx.x;
    const int g0 = blockIdx.x * 2;

    if (tid < 128) {
        int g = tid >> 6, c4 = (tid & 63) * 4;
        float4 v = *(const float4*)&te[(size_t)(g0 + g) * 256 + c4];
        tes[c4 + 0][g] = v.x;
        tes[c4 + 1][g] = v.y;
        tes[c4 + 2][g] = v.z;
        tes[c4 + 3][g] = v.w;
    }
    __syncthreads();

    const int f = tid & 127;
    const int half = tid >> 7;
    const float* W = half ? Wb : Wg;

    ull acc0 = 0ULL, acc1 = 0ULL;
#pragma unroll 8
    for (int k = 0; k < 256; k += 2) {
        float w0 = W[(size_t)k * 128 + f];
        float w1 = W[(size_t)(k + 1) * 128 + f];
        ull t0 = *reinterpret_cast<const ull*>(&tes[k][0]);
        ull t1 = *reinterpret_cast<const ull*>(&tes[k + 1][0]);
        ffma2(acc0, pack2(w0, w0), t0);
        ffma2(acc1, pack2(w1, w1), t1);
    }
    float2 p0 = unpack2(acc0), p1 = unpack2(acc1);
    float add = half ? bb[f] : (bg[f] + 1.0f);
    float* dst = half ? g_beta : g_gamma;
    dst[(g0 + 0) * 128 + f] = p0.x + p1.x + add;
    dst[(g0 + 1) * 128 + f] = p0.y + p1.y + add;
}

// ---------------------------------------------------------------------------
// 5) fused GraphNorm stats + FiLM apply + silu + residual (block per graph)
// ---------------------------------------------------------------------------
__global__ __launch_bounds__(128) void normfinal_kernel(
    const float* __restrict__ x, const int* __restrict__ batch,
    const float* __restrict__ ms,
    const float* __restrict__ gnw, const float* __restrict__ gnb,
    float* __restrict__ out) {
    __shared__ int bounds[2];
    const int g = blockIdx.x;
    if (threadIdx.x < 2) {
        int target = g + threadIdx.x;
        int lo = 0, hi = Nn;
        while (lo < hi) {
            int mid = (lo + hi) >> 1;
            if (batch[mid] < target) lo = mid + 1; else hi = mid;
        }
        bounds[threadIdx.x] = lo;
    }
    __syncthreads();
    const int s = bounds[0], e = bounds[1];
    const int f = threadIdx.x;

    // pass 1: per-feature sum / sumsq over this graph's rows
    float sum0 = 0.f, sq0 = 0.f, sum1 = 0.f, sq1 = 0.f;
    float sum2 = 0.f, sq2 = 0.f, sum3 = 0.f, sq3 = 0.f;
    int n = s;
    for (; n + 3 < e; n += 4) {
        float v0 = g_h[(size_t)n * 128 + f];
        float v1 = g_h[(size_t)(n + 1) * 128 + f];
        float v2 = g_h[(size_t)(n + 2) * 128 + f];
        float v3 = g_h[(size_t)(n + 3) * 128 + f];
        sum0 += v0; sq0 += v0 * v0;
        sum1 += v1; sq1 += v1 * v1;
        sum2 += v2; sq2 += v2 * v2;
        sum3 += v3; sq3 += v3 * v3;
    }
    for (; n < e; ++n) {
        float v0 = g_h[(size_t)n * 128 + f];
        sum0 += v0; sq0 += v0 * v0;
    }
    float sum = (sum0 + sum1) + (sum2 + sum3);
    float sq = (sq0 + sq1) + (sq2 + sq3);

    float ccount = fmaxf((float)(e - s), 1.f);
    float mean = sum / ccount;
    float m2 = sq / ccount;
    float msf = ms[f];
    float var = m2 - (2.f * msf - msf * msf) * mean * mean;
    var = fmaxf(var, 0.f);
    float msub = mean * msf;
    float rstd = rsqrtf(var + 1e-5f);

    float gm = g_gamma[g * 128 + f];
    float bt = g_beta[g * 128 + f];
    float w = gnw[f];
    float b = gnb[f];
    // fold: out = x + silu( (gm*w*rstd)*h + (gm*(b - w*msub*rstd) + bt) )
    float kA = gm * w * rstd;
    float kB = gm * (b - w * msub * rstd) + bt;

    // pass 2 (L2-hot): normalize + film + silu + residual
    for (n = s; n < e; ++n) {
        float h = g_h[(size_t)n * 128 + f];
        float xv = x[(size_t)n * 128 + f];
        float v = kA * h + kB;
        out[(size_t)n * 128 + f] = xv + silu_f(v);
    }
}

// ---------------------------------------------------------------------------
extern "C" void kernel_launch(void* const* d_in, const int* in_sizes, int n_in,
                              void* d_out, int out_size) {
    const float* x   = (const float*)d_in[0];
    const int*   ei  = (const int*)d_in[1];
    const float* ea  = (const float*)d_in[2];
    const int*   bat = (const int*)d_in[3];
    const float* te  = (const float*)d_in[4];
    const float* We  = (const float*)d_in[5];
    const float* be  = (const float*)d_in[6];
    const float* W1  = (const float*)d_in[7];
    const float* b1  = (const float*)d_in[8];
    const float* W2  = (const float*)d_in[9];
    const float* b2  = (const float*)d_in[10];
    const float* gnw = (const float*)d_in[11];
    const float* gnb = (const float*)d_in[12];
    const float* gms = (const float*)d_in[13];
    const float* Wg  = (const float*)d_in[14];
    const float* bg  = (const float*)d_in[15];
    const float* Wb  = (const float*)d_in[16];
    const float* bb  = (const float*)d_in[17];
    float* out = (float*)d_out;

    cudaFuncSetAttribute((const void*)mlp_kernel,
                         cudaFuncAttributeMaxDynamicSharedMemorySize, MLP_SMEM);

    copy_kernel<<<12500, 256>>>(x);
    edge_kernel<<<EK_GRID, 256>>>(x, ei, ea, We, be);
    mlp_kernel<<<(Nn + 127) / 128, 256, MLP_SMEM>>>(W1, b1, W2, b2);
    film_kernel<<<Gg / 2, 256>>>(te, Wg, bg, Wb, bb);
    normfinal_kernel<<<Gg, 128>>>(x, bat, gms, gnw, gnb, out);
}

// round 15
// speedup vs baseline: 1.2941x; 1.2707x over previous
#include <cuda_runtime.h>
#include <cuda_bf16.h>
#include <cstdint>
#include <math.h>

#define Nn 100000
#define Ee 1600000
#define Hh 128
#define Gg 512
#define TDd 256
#define NTILES 12500   // Ee / 128
#define EK_GRID 296

typedef unsigned long long ull;

// Scratch (device globals — no allocation allowed)
__device__ float g_agg[(size_t)Nn * Hh];
__device__ float g_h[(size_t)Nn * Hh];
__device__ float g_mean[Gg * Hh];
__device__ float g_rstd[Gg * Hh];
__device__ float g_gamma[Gg * Hh];
__device__ float g_beta[Gg * Hh];

__device__ __forceinline__ float silu_f(float v) {
    return v * (1.0f / (1.0f + __expf(-v)));
}

// ---- packed f32x2 helpers --------------------------------------------------
__device__ __forceinline__ ull pack2(float x, float y) {
    ull r;
    asm("mov.b64 %0, {%1, %2};" : "=l"(r) : "f"(x), "f"(y));
    return r;
}
__device__ __forceinline__ void ffma2(ull& d, ull a, ull b) {
    asm("fma.rn.f32x2 %0, %1, %2, %0;" : "+l"(d) : "l"(a), "l"(b));
}
__device__ __forceinline__ float2 unpack2(ull v) {
    float2 r;
    asm("mov.b64 {%0, %1}, %2;" : "=f"(r.x), "=f"(r.y) : "l"(v));
    return r;
}

// ---- warp-level bf16 mma -----------------------------------------------------
__device__ __forceinline__ void mma_bf16(float* c, const uint32_t* a,
                                         uint32_t b0, uint32_t b1) {
    asm("mma.sync.aligned.m16n8k16.row.col.f32.bf16.bf16.f32 "
        "{%0,%1,%2,%3}, {%4,%5,%6,%7}, {%8,%9}, {%0,%1,%2,%3};"
        : "+f"(c[0]), "+f"(c[1]), "+f"(c[2]), "+f"(c[3])
        : "r"(a[0]), "r"(a[1]), "r"(a[2]), "r"(a[3]), "r"(b0), "r"(b1));
}

__device__ __forceinline__ void cvt8(const float* v, uint4* hi, uint4* lo) {
    uint32_t h[4], l[4];
#pragma unroll
    for (int i = 0; i < 4; ++i) {
        float a = v[2 * i], b = v[2 * i + 1];
        __nv_bfloat16 ha = __float2bfloat16(a), hb = __float2bfloat16(b);
        __nv_bfloat16 la = __float2bfloat16(a - __bfloat162float(ha));
        __nv_bfloat16 lb = __float2bfloat16(b - __bfloat162float(hb));
        h[i] = ((uint32_t)__bfloat16_as_ushort(hb) << 16) | (uint32_t)__bfloat16_as_ushort(ha);
        l[i] = ((uint32_t)__bfloat16_as_ushort(lb) << 16) | (uint32_t)__bfloat16_as_ushort(la);
    }
    *hi = make_uint4(h[0], h[1], h[2], h[3]);
    *lo = make_uint4(l[0], l[1], l[2], l[3]);
}

__device__ __forceinline__ void cvt2(float a, float b, uint32_t* hp, uint32_t* lp) {
    __nv_bfloat16 ha = __float2bfloat16(a), hb = __float2bfloat16(b);
    __nv_bfloat16 la = __float2bfloat16(a - __bfloat162float(ha));
    __nv_bfloat16 lb = __float2bfloat16(b - __bfloat162float(hb));
    *hp = ((uint32_t)__bfloat16_as_ushort(hb) << 16) | (uint32_t)__bfloat16_as_ushort(ha);
    *lp = ((uint32_t)__bfloat16_as_ushort(lb) << 16) | (uint32_t)__bfloat16_as_ushort(la);
}

// Stage a (col n, k-half ks) strip of B/W into FRAGMENT-ORDERED smem.
__device__ __forceinline__ void stage_bfrag(char* fh, char* fl, int n, int ks,
                                            const float* w) {
    uint4 h0, l0, h1, l1;
    cvt8(&w[0], &h0, &l0);
    cvt8(&w[8], &h1, &l1);
    const int nf = n >> 3, g = n & 7;
    uint32_t base = (uint32_t)(nf * 32 + g * 4) * 16 + (uint32_t)ks * 8;
    const uint32_t hw[4] = {h0.x, h0.y, h0.z, h0.w};
    const uint32_t hz[4] = {h1.x, h1.y, h1.z, h1.w};
    const uint32_t lw[4] = {l0.x, l0.y, l0.z, l0.w};
    const uint32_t lz[4] = {l1.x, l1.y, l1.z, l1.w};
#pragma unroll
    for (int t = 0; t < 4; ++t) {
        *(uint2*)(fh + base + t * 16) = make_uint2(hw[t], hz[t]);
        *(uint2*)(fl + base + t * 16) = make_uint2(lw[t], lz[t]);
    }
}

// ---- cp.async helpers (Ampere+, OK on baseline sm_100) ----------------------
__device__ __forceinline__ uint32_t smem_u32(const void* p) {
    uint32_t a;
    asm("{ .reg .u64 t; cvta.to.shared.u64 t, %1; cvt.u32.u64 %0, t; }"
        : "=r"(a) : "l"(p));
    return a;
}
__device__ __forceinline__ void cp_async16(uint32_t saddr, const void* gaddr) {
    asm volatile("cp.async.cg.shared.global [%0], [%1], 16;"
                 :: "r"(saddr), "l"(gaddr) : "memory");
}
__device__ __forceinline__ void cp_commit() {
    asm volatile("cp.async.commit_group;" ::: "memory");
}
__device__ __forceinline__ void cp_wait0() {
    asm volatile("cp.async.wait_group 0;" ::: "memory");
}

// edge kernel smem layout (bytes); A staged as RAW fp32, pitch 144B (16B-aligned)
#define APITCH 144
#define ABUF   (128 * APITCH)      // 18432 per buffer
#define SBE    0
#define SSRC   512                 // [2][128] int
#define SDST   1536                // [2][128] int
#define SFBH   2560                // 8192
#define SFBL   10752               // 8192
#define SA     18944               // [2] x 18432
#define EKSM   (18944 + 2 * ABUF)  // 55808

__device__ __forceinline__ void stage_tile_async(
    uint32_t sb, const float* __restrict__ ea, const int* __restrict__ ei,
    int e0, int buf, int tid) {
#pragma unroll
    for (int i = 0; i < 4; ++i) {
        int ch = tid + 256 * i;          // 1024 chunks of 16B
        int row = ch >> 3, c = ch & 7;
        cp_async16(sb + SA + (uint32_t)buf * ABUF + (uint32_t)row * APITCH + (uint32_t)c * 16,
                   ea + (size_t)(e0 + row) * 32 + c * 4);
    }
    if (tid < 32) {
        cp_async16(sb + SSRC + (uint32_t)buf * 512 + (uint32_t)tid * 16, ei + e0 + tid * 4);
    } else if (tid < 64) {
        int l = tid - 32;
        cp_async16(sb + SDST + (uint32_t)buf * 512 + (uint32_t)l * 16, ei + Ee + e0 + l * 4);
    }
}

// ---------------------------------------------------------------------------
// 1) init: g_agg = x
// ---------------------------------------------------------------------------
__global__ void copy_kernel(const float* __restrict__ x) {
    size_t i = (size_t)blockIdx.x * blockDim.x + threadIdx.x;
    ((float4*)g_agg)[i] = ((const float4*)x)[i];
}

// ---------------------------------------------------------------------------
// 2) edge kernel v5: cp.async double-buffered fp32 A; cvt at frag-load time.
// ---------------------------------------------------------------------------
__global__ __launch_bounds__(256, 2) void edge_kernel(
    const float* __restrict__ x, const int* __restrict__ ei,
    const float* __restrict__ ea, const float* __restrict__ We,
    const float* __restrict__ be) {
    extern __shared__ __align__(16) char smem[];
    const int tid = threadIdx.x;
    const int wid = tid >> 5;
    const int lane = tid & 31;
    const uint32_t sb = smem_u32(smem);

    float* be_s = (float*)(smem + SBE);
    int* src_s = (int*)(smem + SSRC);
    int* dst_s = (int*)(smem + SDST);

    if (tid < 128) be_s[tid] = be[tid];

    // stage B = We^T hi/lo in fragment order, once
    {
        int n = tid >> 1;
        int ks = tid & 1;
        float w[16];
#pragma unroll
        for (int j = 0; j < 16; ++j) w[j] = We[(size_t)(ks * 16 + j) * 128 + n];
        stage_bfrag(smem + SFBH, smem + SFBL, n, ks, w);
    }

    // prologue: async-stage tile0 into buf 0
    stage_tile_async(sb, ea, ei, blockIdx.x * 128, 0, tid);
    cp_commit();

    const int g = lane >> 2;
    const int t = lane & 3;
    const int q = t >> 1;
    const int odd = t & 1;
    const int mb = wid * 16;

    int p = 0;
    for (int tile = blockIdx.x; tile < NTILES; tile += gridDim.x, p ^= 1) {
        cp_wait0();
        __syncthreads();

        // kick off next tile into the other buffer (no register cost)
        const int ntile = tile + gridDim.x;
        if (ntile < NTILES)
            stage_tile_async(sb, ea, ei, ntile * 128, p ^ 1, tid);
        cp_commit();

        // fragment loads from raw fp32 buf p, converting hi/lo in registers
        uint32_t afh[2][4], afl[2][4];
        {
            const char* Ab = smem + SA + (uint32_t)p * ABUF;
            const char* r0p = Ab + (mb + g) * APITCH;
            const char* r1p = r0p + 8 * APITCH;
#pragma unroll
            for (int ks = 0; ks < 2; ++ks) {
                const int k0 = (2 * t + 16 * ks) * 4;  // byte offset of k pair
                float2 p0 = *(const float2*)(r0p + k0);
                float2 p1 = *(const float2*)(r1p + k0);
                float2 p2 = *(const float2*)(r0p + k0 + 32);
                float2 p3 = *(const float2*)(r1p + k0 + 32);
                cvt2(p0.x, p0.y, &afh[ks][0], &afl[ks][0]);
                cvt2(p1.x, p1.y, &afh[ks][1], &afl[ks][1]);
                cvt2(p2.x, p2.y, &afh[ks][2], &afl[ks][2]);
                cvt2(p3.x, p3.y, &afh[ks][3], &afl[ks][3]);
            }
        }

        float c[16][4];
#pragma unroll
        for (int nf = 0; nf < 16; ++nf) {
            c[nf][0] = 0.f; c[nf][1] = 0.f; c[nf][2] = 0.f; c[nf][3] = 0.f;
        }

#pragma unroll
        for (int nf = 0; nf < 16; ++nf) {
            uint4 BH = *(const uint4*)(smem + SFBH + (uint32_t)(nf * 32 + lane) * 16);
            uint4 BL = *(const uint4*)(smem + SFBL + (uint32_t)(nf * 32 + lane) * 16);
            mma_bf16(c[nf], afh[0], BH.x, BH.y);
            mma_bf16(c[nf], afh[1], BH.z, BH.w);
            mma_bf16(c[nf], afh[0], BL.x, BL.y);
            mma_bf16(c[nf], afh[1], BL.z, BL.w);
            mma_bf16(c[nf], afl[0], BH.x, BH.y);
            mma_bf16(c[nf], afl[1], BH.z, BH.w);
        }

        // epilogue: gather x[src] + relu + red (src/dst from partition p)
        const int pb = p * 128;
#pragma unroll
        for (int rs = 0; rs < 2; ++rs) {
            const int el = mb + g + rs * 8;
            const int s = src_s[pb + el];
            const int d = dst_s[pb + el];
            const float* xb = x + (size_t)s * 128;
            float* ob = g_agg + (size_t)d * 128;
#pragma unroll
            for (int pp = 0; pp < 8; ++pp) {
                const int nfe = 2 * pp, nfo = 2 * pp + 1;
                float2 me, mo;
                me.x = c[nfe][rs * 2]; me.y = c[nfe][rs * 2 + 1];
                mo.x = c[nfo][rs * 2]; mo.y = c[nfo][rs * 2 + 1];
                ull send = odd ? pack2(me.x, me.y) : pack2(mo.x, mo.y);
                ull recv = __shfl_xor_sync(0xFFFFFFFFu, send, 1);
                float2 rv = unpack2(recv);
                const int nf = odd ? nfo : nfe;
                float2 lo2 = odd ? rv : me;
                float2 hi2 = odd ? mo : rv;
                const int col = nf * 8 + q * 4;
                float4 xv = *(const float4*)(xb + col);
                float4 bv = *(const float4*)&be_s[col];
                float r0 = fmaxf(xv.x + lo2.x + bv.x, 0.f);
                float r1 = fmaxf(xv.y + lo2.y + bv.y, 0.f);
                float r2 = fmaxf(xv.z + hi2.x + bv.z, 0.f);
                float r3 = fmaxf(xv.w + hi2.y + bv.w, 0.f);
                asm volatile("red.global.add.v4.f32 [%0], {%1,%2,%3,%4};"
                             :: "l"(ob + col), "f"(r0), "f"(r1), "f"(r2), "f"(r3)
                             : "memory");
            }
        }
    }
}

// ---------------------------------------------------------------------------
// 3) fused node MLP (R8 proven: smem-staged A, frag-ordered W)
// ---------------------------------------------------------------------------
#define MP 272
#define MS_AHI 0
#define MS_ALO 34816
#define MS_WFH 69632
#define MS_WFL 77824
#define MS_B1  86016
#define MS_B2  86528
#define MLP_SMEM 87040

extern "C" __global__ __launch_bounds__(256) void mlp_kernel(
    const float* __restrict__ W1, const float* __restrict__ b1,
    const float* __restrict__ W2, const float* __restrict__ b2) {
    extern __shared__ __align__(16) char msm[];
    const int tid = threadIdx.x;
    const int wid = tid >> 5;
    const int lane = tid & 31;
    const int g = lane >> 2;
    const int t = lane & 3;
    const int q = t >> 1;
    const int odd = t & 1;
    const int mb = wid * 16;
    const int r0 = blockIdx.x * 128;

    float* b1s = (float*)(msm + MS_B1);
    float* b2s = (float*)(msm + MS_B2);
    if (tid < 128) b1s[tid] = b1[tid];
    else           b2s[tid - 128] = b2[tid - 128];

    {
        int row = tid >> 1;
        int half = tid & 1;
        int node = r0 + row;
        const float* ap = g_agg + (size_t)node * 128 + half * 64;
#pragma unroll
        for (int gi = 0; gi < 4; ++gi) {
            float v[16];
            if (node < Nn) {
                *(float4*)&v[0]  = *(const float4*)(ap + gi * 16 + 0);
                *(float4*)&v[4]  = *(const float4*)(ap + gi * 16 + 4);
                *(float4*)&v[8]  = *(const float4*)(ap + gi * 16 + 8);
                *(float4*)&v[12] = *(const float4*)(ap + gi * 16 + 12);
            } else {
#pragma unroll
                for (int j = 0; j < 16; ++j) v[j] = 0.f;
            }
            uint4 h0, l0, h1, l1;
            cvt8(&v[0], &h0, &l0);
            cvt8(&v[8], &h1, &l1);
            uint32_t off = (uint32_t)row * MP + (uint32_t)(half * 64 + gi * 16) * 2;
            *(uint4*)(msm + MS_AHI + off)      = h0;
            *(uint4*)(msm + MS_AHI + off + 16) = h1;
            *(uint4*)(msm + MS_ALO + off)      = l0;
            *(uint4*)(msm + MS_ALO + off + 16) = l1;
        }
    }
    __syncthreads();

    float c[16][4];
#pragma unroll
    for (int nf = 0; nf < 16; ++nf) {
        c[nf][0] = 0.f; c[nf][1] = 0.f; c[nf][2] = 0.f; c[nf][3] = 0.f;
    }

    for (int lyr = 0; lyr < 2; ++lyr) {
        const float* W = (lyr == 0) ? W1 : W2;

        for (int kc = 0; kc < 128; kc += 32) {
            {
                int n = tid >> 1;
                int ks = tid & 1;
                float w[16];
#pragma unroll
                for (int j = 0; j < 16; ++j)
                    w[j] = W[(size_t)(kc + ks * 16 + j) * 128 + n];
                stage_bfrag(msm + MS_WFH, msm + MS_WFL, n, ks, w);
            }
            __syncthreads();

            uint32_t afh[2][4], afl[2][4];
            {
                const char* Ah = msm + MS_AHI + (mb + g) * MP + kc * 2 + t * 4;
                const char* Al = msm + MS_ALO + (mb + g) * MP + kc * 2 + t * 4;
#pragma unroll
                for (int ks = 0; ks < 2; ++ks) {
                    int o = ks * 32;
                    afh[ks][0] = *(const uint32_t*)(Ah + o);
                    afh[ks][1] = *(const uint32_t*)(Ah + o + 8 * MP);
                    afh[ks][2] = *(const uint32_t*)(Ah + o + 16);
                    afh[ks][3] = *(const uint32_t*)(Ah + o + 8 * MP + 16);
                    afl[ks][0] = *(const uint32_t*)(Al + o);
                    afl[ks][1] = *(const uint32_t*)(Al + o + 8 * MP);
                    afl[ks][2] = *(const uint32_t*)(Al + o + 16);
                    afl[ks][3] = *(const uint32_t*)(Al + o + 8 * MP + 16);
                }
            }

#pragma unroll
            for (int nf = 0; nf < 16; ++nf) {
                uint4 BH = *(const uint4*)(msm + MS_WFH + (uint32_t)(nf * 32 + lane) * 16);
                uint4 BL = *(const uint4*)(msm + MS_WFL + (uint32_t)(nf * 32 + lane) * 16);
                mma_bf16(c[nf], afh[0], BH.x, BH.y);
                mma_bf16(c[nf], afh[1], BH.z, BH.w);
                mma_bf16(c[nf], afh[0], BL.x, BL.y);
                mma_bf16(c[nf], afh[1], BL.z, BL.w);
                mma_bf16(c[nf], afl[0], BH.x, BH.y);
                mma_bf16(c[nf], afl[1], BH.z, BH.w);
            }
            __syncthreads();
        }

        if (lyr == 0) {
#pragma unroll
            for (int nf = 0; nf < 16; ++nf) {
#pragma unroll
                for (int rs = 0; rs < 2; ++rs) {
                    int row = mb + g + rs * 8;
                    int col = nf * 8 + 2 * t;
                    float m0 = silu_f(c[nf][rs * 2] + b1s[col]);
                    float m1 = silu_f(c[nf][rs * 2 + 1] + b1s[col + 1]);
                    uint32_t hp, lp;
                    cvt2(m0, m1, &hp, &lp);
                    uint32_t off = (uint32_t)row * MP + (uint32_t)col * 2;
                    *(uint32_t*)(msm + MS_AHI + off) = hp;
                    *(uint32_t*)(msm + MS_ALO + off) = lp;
                    c[nf][rs * 2] = 0.f;
                    c[nf][rs * 2 + 1] = 0.f;
                }
            }
            __syncthreads();
        }
    }

#pragma unroll
    for (int rs = 0; rs < 2; ++rs) {
        const int node = r0 + mb + g + rs * 8;
        float* ob = g_h + (size_t)node * 128;
#pragma unroll
        for (int p = 0; p < 8; ++p) {
            const int nfe = 2 * p, nfo = 2 * p + 1;
            float2 me, mo;
            me.x = c[nfe][rs * 2]; me.y = c[nfe][rs * 2 + 1];
            mo.x = c[nfo][rs * 2]; mo.y = c[nfo][rs * 2 + 1];
            ull send = odd ? pack2(me.x, me.y) : pack2(mo.x, mo.y);
            ull recv = __shfl_xor_sync(0xFFFFFFFFu, send, 1);
            float2 rv = unpack2(recv);
            const int nf = odd ? nfo : nfe;
            float2 lo2 = odd ? rv : me;
            float2 hi2 = odd ? mo : rv;
            const int col = nf * 8 + q * 4;
            if (node < Nn) {
                float4 o;
                o.x = lo2.x + b2s[col + 0];
                o.y = lo2.y + b2s[col + 1];
                o.z = hi2.x + b2s[col + 2];
                o.w = hi2.y + b2s[col + 3];
                *(float4*)(ob + col) = o;
            }
        }
    }
}

// ---------------------------------------------------------------------------
// 4) GraphNorm stats (R8 proven)
// ---------------------------------------------------------------------------
__global__ void stats_kernel(const int* __restrict__ batch,
                             const float* __restrict__ ms) {
    __shared__ int bounds[2];
    const int g = blockIdx.x;
    if (threadIdx.x < 2) {
        int target = g + threadIdx.x;
        int lo = 0, hi = Nn;
        while (lo < hi) {
            int mid = (lo + hi) >> 1;
            if (batch[mid] < target) lo = mid + 1; else hi = mid;
        }
        bounds[threadIdx.x] = lo;
    }
    __syncthreads();
    const int s = bounds[0], e = bounds[1];
    const int f = threadIdx.x;

    float sum0 = 0.f, sq0 = 0.f, sum1 = 0.f, sq1 = 0.f;
    float sum2 = 0.f, sq2 = 0.f, sum3 = 0.f, sq3 = 0.f;
    int n = s;
    for (; n + 3 < e; n += 4) {
        float v0 = g_h[(size_t)n * 128 + f];
        float v1 = g_h[(size_t)(n + 1) * 128 + f];
        float v2 = g_h[(size_t)(n + 2) * 128 + f];
        float v3 = g_h[(size_t)(n + 3) * 128 + f];
        sum0 += v0; sq0 += v0 * v0;
        sum1 += v1; sq1 += v1 * v1;
        sum2 += v2; sq2 += v2 * v2;
        sum3 += v3; sq3 += v3 * v3;
    }
    for (; n < e; ++n) {
        float v0 = g_h[(size_t)n * 128 + f];
        sum0 += v0; sq0 += v0 * v0;
    }
    float sum = (sum0 + sum1) + (sum2 + sum3);
    float sq = (sq0 + sq1) + (sq2 + sq3);

    float c = fmaxf((float)(e - s), 1.f);
    float mean = sum / c;
    float m2 = sq / c;
    float msf = ms[f];
    float var = m2 - (2.f * msf - msf * msf) * mean * mean;
    var = fmaxf(var, 0.f);
    g_mean[g * 128 + f] = mean * msf;
    g_rstd[g * 128 + f] = rsqrtf(var + 1e-5f);
}

// ---------------------------------------------------------------------------
// 5) FiLM params: 2 graphs per block (proven config)
// ---------------------------------------------------------------------------
__global__ __launch_bounds__(256) void film_kernel(
    const float* __restrict__ te,
    const float* __restrict__ Wg, const float* __restrict__ bg,
    const float* __restrict__ Wb, const float* __restrict__ bb) {
    __shared__ float tes[256][2];
    const int tid = threadIdx.x;
    const int g0 = blockIdx.x * 2;

    if (tid < 128) {
        int g = tid >> 6, c4 = (tid & 63) * 4;
        float4 v = *(const float4*)&te[(size_t)(g0 + g) * 256 + c4];
        tes[c4 + 0][g] = v.x;
        tes[c4 + 1][g] = v.y;
        tes[c4 + 2][g] = v.z;
        tes[c4 + 3][g] = v.w;
    }
    __syncthreads();

    const int f = tid & 127;
    const int half = tid >> 7;
    const float* W = half ? Wb : Wg;

    ull acc0 = 0ULL, acc1 = 0ULL;
#pragma unroll 8
    for (int k = 0; k < 256; k += 2) {
        float w0 = W[(size_t)k * 128 + f];
        float w1 = W[(size_t)(k + 1) * 128 + f];
        ull t0 = *reinterpret_cast<const ull*>(&tes[k][0]);
        ull t1 = *reinterpret_cast<const ull*>(&tes[k + 1][0]);
        ffma2(acc0, pack2(w0, w0), t0);
        ffma2(acc1, pack2(w1, w1), t1);
    }
    float2 p0 = unpack2(acc0), p1 = unpack2(acc1);
    float add = half ? bb[f] : (bg[f] + 1.0f);
    float* dst = half ? g_beta : g_gamma;
    dst[(g0 + 0) * 128 + f] = p0.x + p1.x + add;
    dst[(g0 + 1) * 128 + f] = p0.y + p1.y + add;
}

// ---------------------------------------------------------------------------
// 6) final elementwise (R8 proven)
// ---------------------------------------------------------------------------
__global__ void final_kernel(const float* __restrict__ x,
                             const int* __restrict__ batch,
                             const float* __restrict__ gnw,
                             const float* __restrict__ gnb,
                             float* __restrict__ out) {
    int i = blockIdx.x * blockDim.x + threadIdx.x;
    int n = i >> 5;
    int f4 = (i & 31) * 4;
    int g = batch[n];

    float4 h4 = *(float4*)&g_h[(size_t)n * 128 + f4];
    float4 x4 = *(const float4*)&x[(size_t)n * 128 + f4];
    float4 mn = *(float4*)&g_mean[g * 128 + f4];
    float4 rs = *(float4*)&g_rstd[g * 128 + f4];
    float4 gm = *(float4*)&g_gamma[g * 128 + f4];
    float4 bt = *(float4*)&g_beta[g * 128 + f4];
    float4 w4 = *(const float4*)&gnw[f4];
    float4 b4 = *(const float4*)&gnb[f4];

    float4 o;
    o.x = x4.x + silu_f(gm.x * (w4.x * ((h4.x - mn.x) * rs.x) + b4.x) + bt.x);
    o.y = x4.y + silu_f(gm.y * (w4.y * ((h4.y - mn.y) * rs.y) + b4.y) + bt.y);
    o.z = x4.z + silu_f(gm.z * (w4.z * ((h4.z - mn.z) * rs.z) + b4.z) + bt.z);
    o.w = x4.w + silu_f(gm.w * (w4.w * ((h4.w - mn.w) * rs.w) + b4.w) + bt.w);
    *(float4*)&out[(size_t)n * 128 + f4] = o;
}

// ---------------------------------------------------------------------------
extern "C" void kernel_launch(void* const* d_in, const int* in_sizes, int n_in,
                              void* d_out, int out_size) {
    const float* x   = (const float*)d_in[0];
    const int*   ei  = (const int*)d_in[1];
    const float* ea  = (const float*)d_in[2];
    const int*   bat = (const int*)d_in[3];
    const float* te  = (const float*)d_in[4];
    const float* We  = (const float*)d_in[5];
    const float* be  = (const float*)d_in[6];
    const float* W1  = (const float*)d_in[7];
    const float* b1  = (const float*)d_in[8];
    const float* W2  = (const float*)d_in[9];
    const float* b2  = (const float*)d_in[10];
    const float* gnw = (const float*)d_in[11];
    const float* gnb = (const float*)d_in[12];
    const float* gms = (const float*)d_in[13];
    const float* Wg  = (const float*)d_in[14];
    const float* bg  = (const float*)d_in[15];
    const float* Wb  = (const float*)d_in[16];
    const float* bb  = (const float*)d_in[17];
    float* out = (float*)d_out;

    cudaFuncSetAttribute((const void*)edge_kernel,
                         cudaFuncAttributeMaxDynamicSharedMemorySize, EKSM);
    cudaFuncSetAttribute((const void*)mlp_kernel,
                         cudaFuncAttributeMaxDynamicSharedMemorySize, MLP_SMEM);

    copy_kernel<<<12500, 256>>>(x);
    edge_kernel<<<EK_GRID, 256, EKSM>>>(x, ei, ea, We, be);
    mlp_kernel<<<(Nn + 127) / 128, 256, MLP_SMEM>>>(W1, b1, W2, b2);
    film_kernel<<<Gg / 2, 256>>>(te, Wg, bg, Wb, bb);
    stats_kernel<<<Gg, 128>>>(bat, gms);
    final_kernel<<<12500, 256>>>(x, bat, gnw, gnb, out);
}